// round 2
// baseline (speedup 1.0000x reference)
#include <cuda_runtime.h>

#define BB 8
#define NNROWS 4000
#define CC 80
#define NC (NNROWS*CC)        // 320000
#define KPRE 2048
#define DETN 100
#define NWORDS (KPRE/64)      // 32
#define CLIPF 4.135166556742356f

// ---------------- device scratch (static, no allocation) ----------------
__device__ unsigned long long g_keys[BB][NC];          // 20.5 MB
__device__ unsigned int       g_hist[8][BB][256];
__device__ unsigned long long g_prefix[BB];
__device__ int                g_kth[BB];
__device__ int                g_cnt[BB];
__device__ unsigned long long g_topkeys[BB][KPRE];
__device__ float              g_scores[BB][KPRE];
__device__ float4             g_boxes[BB][KPRE];
__device__ float4             g_nmsb[BB][KPRE];
__device__ int                g_labels[BB][KPRE];
__device__ int                g_vcount[BB];
__device__ unsigned long long g_mask[BB][KPRE][NWORDS]; // 4 MB

// ---------------- helpers ----------------
__device__ __forceinline__ unsigned f2ord(float f) {
    unsigned u = __float_as_uint(f);
    return (u & 0x80000000u) ? ~u : (u | 0x80000000u);
}
__device__ __forceinline__ float ord2f(unsigned o) {
    unsigned u = (o & 0x80000000u) ? (o ^ 0x80000000u) : ~o;
    return __uint_as_float(u);
}

__device__ __forceinline__ void decode_box(float d0, float d1, float d2, float d3,
                                           float4 p,
                                           float& x1, float& y1, float& x2, float& y2) {
    float w  = p.z - p.x;
    float h  = p.w - p.y;
    float cx = p.x + 0.5f * w;
    float cy = p.y + 0.5f * h;
    float dx = d0 / 10.0f;
    float dy = d1 / 10.0f;
    float dw = fminf(d2 / 5.0f, CLIPF);
    float dh = fminf(d3 / 5.0f, CLIPF);
    float pcx = dx * w + cx;
    float pcy = dy * h + cy;
    float pw  = expf(dw) * w;
    float ph  = expf(dh) * h;
    x1 = pcx - 0.5f * pw;
    y1 = pcy - 0.5f * ph;
    x2 = pcx + 0.5f * pw;
    y2 = pcy + 0.5f * ph;
}

// ---------------- kernels ----------------
__global__ void k_init() {
    int t = blockIdx.x * blockDim.x + threadIdx.x;
    int H = 8 * BB * 256;
    unsigned* h = (unsigned*)g_hist;
    for (int i = t; i < H; i += gridDim.x * blockDim.x) h[i] = 0u;
    if (t < BB) { g_prefix[t] = 0ull; g_kth[t] = KPRE; g_cnt[t] = 0; }
}

// one warp per proposal row: softmax, per-class decode for validity, emit keys
__global__ __launch_bounds__(256) void k_scorekey(const float* __restrict__ label,
                                                  const float* __restrict__ bbox,
                                                  const float* __restrict__ props) {
    int img  = blockIdx.y;
    int warp = threadIdx.x >> 5;
    int lane = threadIdx.x & 31;
    int row  = blockIdx.x * 8 + warp;
    if (row >= NNROWS) return;

    const float* L = label + ((size_t)img * NNROWS + row) * (CC + 1);

    float m = -3.402823466e38f;
    for (int c = lane; c < CC + 1; c += 32) m = fmaxf(m, L[c]);
#pragma unroll
    for (int o = 16; o > 0; o >>= 1) m = fmaxf(m, __shfl_xor_sync(0xffffffffu, m, o));

    float ssum = 0.0f;
    for (int c = lane; c < CC + 1; c += 32) ssum += expf(L[c] - m);
#pragma unroll
    for (int o = 16; o > 0; o >>= 1) ssum += __shfl_xor_sync(0xffffffffu, ssum, o);

    float4 p = ((const float4*)props)[img * NNROWS + row];
    // deltas for class c (1-based) start at 4*(c+1); row base is 16B-aligned (324*4B=1296B)
    const float4* D4 = (const float4*)(bbox + ((size_t)img * NNROWS + row) * ((CC + 1) * 4) + 4);

    for (int c = lane; c < CC; c += 32) {
        float sc = expf(L[c + 1] - m) / ssum;
        float4 d = D4[c];
        float x1, y1, x2, y2;
        decode_box(d.x, d.y, d.z, d.w, p, x1, y1, x2, y2);
        float area = (y2 - y1) * (x2 - x1);
        float masked = ((sc > 0.01f) && (area > 0.1f)) ? sc : -1.0f;
        unsigned idx = (unsigned)(row * CC + c);
        unsigned long long key =
            ((unsigned long long)f2ord(masked) << 32) | (unsigned long long)(0xFFFFFFFFu - idx);
        g_keys[img][idx] = key;
    }
}

__global__ __launch_bounds__(256) void k_hist(int r) {
    int img = blockIdx.y;
    __shared__ unsigned sh[256];
    if (threadIdx.x < 256) sh[threadIdx.x] = 0u;
    __syncthreads();
    unsigned long long prefix = g_prefix[img];
    int dsh = 56 - 8 * r;
    for (int i = blockIdx.x * blockDim.x + threadIdx.x; i < NC; i += gridDim.x * blockDim.x) {
        unsigned long long key = g_keys[img][i];
        if (r == 0 || (key >> (dsh + 8)) == prefix)
            atomicAdd(&sh[(unsigned)(key >> dsh) & 0xFFu], 1u);
    }
    __syncthreads();
    if (threadIdx.x < 256 && sh[threadIdx.x])
        atomicAdd(&g_hist[r][img][threadIdx.x], sh[threadIdx.x]);
}

__global__ void k_select(int r) {
    if (threadIdx.x != 0) return;
    int img = blockIdx.x;
    int k = g_kth[img];
    int acc = 0, d = 0;
    for (int dd = 255; dd >= 0; --dd) {
        int c = (int)g_hist[r][img][dd];
        if (acc + c >= k) { d = dd; break; }
        acc += c;
    }
    g_prefix[img] = (g_prefix[img] << 8) | (unsigned long long)d;
    g_kth[img] = k - acc;
}

__global__ __launch_bounds__(256) void k_compact() {
    int img = blockIdx.y;
    unsigned long long pivot = g_prefix[img];
    for (int i = blockIdx.x * blockDim.x + threadIdx.x; i < NC; i += gridDim.x * blockDim.x) {
        unsigned long long key = g_keys[img][i];
        if (key >= pivot) {
            int p = atomicAdd(&g_cnt[img], 1);
            g_topkeys[img][p] = key;
        }
    }
}

// sort 2048 keys descending (bitonic on complemented keys), decode selected boxes
__global__ __launch_bounds__(1024) void k_sortdecode(const float* __restrict__ bbox,
                                                     const float* __restrict__ props) {
    int img = blockIdx.x;
    int tid = threadIdx.x;
    __shared__ unsigned long long s[KPRE];
    s[tid]        = ~g_topkeys[img][tid];
    s[tid + 1024] = ~g_topkeys[img][tid + 1024];
    __syncthreads();

    for (int ksz = 2; ksz <= KPRE; ksz <<= 1) {
        for (int j = ksz >> 1; j > 0; j >>= 1) {
            for (int i = tid; i < KPRE; i += 1024) {
                int ixj = i ^ j;
                if (ixj > i) {
                    unsigned long long a = s[i], b = s[ixj];
                    bool up = ((i & ksz) == 0);
                    if ((a > b) == up) { s[i] = b; s[ixj] = a; }
                }
            }
            __syncthreads();
        }
    }

    for (int i = tid; i < KPRE; i += 1024) {
        unsigned long long key = ~s[i];
        float sc = ord2f((unsigned)(key >> 32));
        unsigned idx = 0xFFFFFFFFu - (unsigned)(key & 0xFFFFFFFFull);
        int n = (int)(idx / CC);
        int c = (int)(idx - (unsigned)n * CC);
        float4 p = ((const float4*)props)[img * NNROWS + n];
        const float4* D4 = (const float4*)(bbox + ((size_t)img * NNROWS + n) * ((CC + 1) * 4) + 4);
        float4 d = D4[c];
        float x1, y1, x2, y2;
        decode_box(d.x, d.y, d.z, d.w, p, x1, y1, x2, y2);
        g_scores[img][i] = sc;
        g_boxes[img][i]  = make_float4(x1, y1, x2, y2);
        float off = (float)(c + 1) * 4096.0f;
        g_nmsb[img][i]   = make_float4(x1 + off, y1 + off, x2 + off, y2 + off);
        g_labels[img][i] = c + 1;

        float nx = (i < KPRE - 1) ? ord2f((unsigned)((~s[i + 1]) >> 32)) : -2.0f;
        if (i == 0 && !(sc > 0.0f)) g_vcount[img] = 0;
        if (sc > 0.0f && (i == KPRE - 1 || !(nx > 0.0f))) g_vcount[img] = i + 1;
    }
}

__global__ __launch_bounds__(64) void k_mask() {
    int img = blockIdx.z;
    int bx  = blockIdx.x;   // col chunk
    int by  = blockIdx.y;   // row chunk
    int t   = threadIdx.x;
    __shared__ float4 cb[64];
    cb[t] = g_nmsb[img][bx * 64 + t];
    __syncthreads();

    int row = by * 64 + t;
    float4 a = g_nmsb[img][row];
    float aw = fmaxf(a.z - a.x, 0.0f), ah = fmaxf(a.w - a.y, 0.0f);
    float areaA = aw * ah;

    unsigned long long bits = 0ull;
#pragma unroll 8
    for (int j = 0; j < 64; j++) {
        int col = bx * 64 + j;
        if (col > row) {
            float4 b = cb[j];
            float bw = fmaxf(b.z - b.x, 0.0f), bh = fmaxf(b.w - b.y, 0.0f);
            float areaB = bw * bh;
            float w = fmaxf(fminf(a.z, b.z) - fmaxf(a.x, b.x), 0.0f);
            float h = fmaxf(fminf(a.w, b.w) - fmaxf(a.y, b.y), 0.0f);
            float inter = w * h;
            float uni = areaA + areaB - inter;
            if (inter / fmaxf(uni, 1e-9f) > 0.5f) bits |= (1ull << j);
        }
    }
    g_mask[img][row][bx] = bits;
}

__global__ __launch_bounds__(128) void k_reduceout(float* __restrict__ out) {
    int img = blockIdx.x;
    int tid = threadIdx.x;
    __shared__ unsigned long long skeep[NWORDS];
    __shared__ int sdet[DETN];
    __shared__ int sdetk[DETN];

    if (tid < 32) {
        int V = g_vcount[img];
        int base = tid * 64;
        unsigned long long rm;
        if (V <= base)           rm = ~0ull;
        else if (V >= base + 64) rm = 0ull;
        else                     rm = (~0ull) << (V - base);

        unsigned long long nxt = g_mask[img][0][tid];
        for (int i = 0; i < KPRE; i++) {
            unsigned long long cur = nxt;
            if (i + 1 < KPRE) nxt = g_mask[img][i + 1][tid];
            unsigned long long w = __shfl_sync(0xffffffffu, rm, i >> 6);
            if (!((w >> (i & 63)) & 1ull)) rm |= cur;
        }
        skeep[tid] = ~rm;
    }
    __syncthreads();

    if (tid == 0) {
        int nk = 0;
        for (int i = 0; i < KPRE && nk < DETN; i++)
            if ((skeep[i >> 6] >> (i & 63)) & 1ull) { sdet[nk] = i; sdetk[nk] = 1; nk++; }
        for (int i = 0; i < KPRE && nk < DETN; i++)
            if (!((skeep[i >> 6] >> (i & 63)) & 1ull)) { sdet[nk] = i; sdetk[nk] = 0; nk++; }
    }
    __syncthreads();

    if (tid < DETN) {
        int i = sdet[tid];
        float4 b = g_boxes[img][i];
        int o = img * DETN + tid;
        out[o * 4 + 0] = b.x;
        out[o * 4 + 1] = b.y;
        out[o * 4 + 2] = b.z;
        out[o * 4 + 3] = b.w;
        out[BB * DETN * 4 + o] = sdetk[tid] ? g_scores[img][i] : -1.0f;
        out[BB * DETN * 5 + o] = (float)g_labels[img][i];
    }
}

// ---------------- launch ----------------
extern "C" void kernel_launch(void* const* d_in, const int* in_sizes, int n_in,
                              void* d_out, int out_size) {
    const float* label = (const float*)d_in[0];
    const float* bbox  = (const float*)d_in[1];
    const float* props = (const float*)d_in[2];
    float* out = (float*)d_out;

    k_init<<<32, 256>>>();
    k_scorekey<<<dim3(500, BB), 256>>>(label, bbox, props);
    for (int r = 0; r < 8; r++) {
        k_hist<<<dim3(80, BB), 256>>>(r);
        k_select<<<BB, 32>>>(r);
    }
    k_compact<<<dim3(80, BB), 256>>>();
    k_sortdecode<<<BB, 1024>>>(bbox, props);
    k_mask<<<dim3(32, 32, BB), 64>>>();
    k_reduceout<<<BB, 128>>>(out);
}